// round 2
// baseline (speedup 1.0000x reference)
#include <cuda_runtime.h>

// Problem constants
#define T_    256
#define B_    128
#define E_    1024
#define H_    1024
#define K_    2048          // E + H
#define N4_   4096          // 4 * H
#define NSPLIT 8
#define KSPL  256           // K per split (2048 / 8)
#define BM    128
#define BN    128
#define BK    16
#define LDA_S 132           // padded smem row stride (floats)
#define LDB_S 132

typedef unsigned long long ull;

// Scratch (static device memory — no allocations allowed)
__device__ float g_zpart[NSPLIT * B_ * N4_];  // 16 MB: K-split partial sums of z
__device__ float g_c[B_ * H_];                // LSTM cell state

// ---------------- packed fp32x2 helpers (Blackwell FFMA2 path) ----------------
__device__ __forceinline__ ull pack2(float lo, float hi) {
    ull r;
    asm("mov.b64 %0, {%1, %2};"
        : "=l"(r) : "r"(__float_as_uint(lo)), "r"(__float_as_uint(hi)));
    return r;
}
__device__ __forceinline__ ull ffma2(ull a, ull b, ull c) {
    ull d;
    asm("fma.rn.f32x2 %0, %1, %2, %3;" : "=l"(d) : "l"(a), "l"(b), "l"(c));
    return d;
}

// ---------------- init: h_0 = 0 (output slice t=0), c = 0 ----------------
__global__ void init_kernel(float* __restrict__ out) {
    int idx = blockIdx.x * blockDim.x + threadIdx.x;
    if (idx < B_ * H_) {
        out[idx] = 0.0f;   // output[0] = h0 = zeros
        g_c[idx] = 0.0f;
    }
}

// ---------------- per-step GEMM: z_partial[ks] = xh_slice @ W_slice^T ----------------
// grid = (32 n-tiles, 8 k-splits), 256 threads, C tile 128x128, 8x8 microtile
// K-splits 0..3 read x_t = embeds[t]; 4..7 read h_{t-1} = out[t-1].
__global__ __launch_bounds__(256, 2) void gemm_step(
    const float* __restrict__ embeds,
    const float* __restrict__ Wg, const float* __restrict__ Wi,
    const float* __restrict__ Wf, const float* __restrict__ Wo,
    const float* __restrict__ out, int t)
{
    __shared__ float As[2][BK * LDA_S];
    __shared__ float Bs[2][BK * LDB_S];

    const int ntile = blockIdx.x;   // 0..31 -> cols of z (4096 / 128)
    const int ks    = blockIdx.y;   // 0..7  -> K split
    const int tid   = threadIdx.x;

    // B operand: each 128-wide n-tile lies entirely inside one gate's weight
    const int gate    = ntile >> 3;
    const float* Wsel = (gate == 0) ? Wg : (gate == 1) ? Wi : (gate == 2) ? Wf : Wo;
    const int rowbase = (ntile & 7) * BM;       // row within the 1024-row gate weight
    const int kbase   = ks * KSPL;              // column offset in W (0..2047)

    // A operand: virtual xh = [x_t, h_prev]
    const float* Aptr;
    int acol0;
    if (ks < 4) { Aptr = embeds + (size_t)t * B_ * E_;        acol0 = kbase;        }
    else        { Aptr = out    + (size_t)(t - 1) * B_ * H_;  acol0 = kbase - 1024; }

    // loader mapping: 256 threads load a 128x16 tile (2 float4 each) per operand
    const int lkq  = tid & 3;    // which float4 column group (0..3) of the 16-wide tile
    const int lrow = tid >> 2;   // 0..63 (and +64)

    // compute mapping: 16x16 thread grid, 8x8 micro-tile (4 low + 4 at +64 each dim)
    const int tx = tid & 15;
    const int ty = tid >> 4;

    ull acc[8][4];
#pragma unroll
    for (int i = 0; i < 8; ++i)
#pragma unroll
        for (int j = 0; j < 4; ++j) acc[i][j] = 0ull;

    float4 aR0, aR1, bR0, bR1;
    const float4* A4 = (const float4*)Aptr;
    const float4* B4 = (const float4*)Wsel;

    // prologue: load stage 0
    aR0 = A4[(size_t)lrow * 256 + (acol0 >> 2) + lkq];
    aR1 = A4[(size_t)(lrow + 64) * 256 + (acol0 >> 2) + lkq];
    bR0 = B4[(size_t)(rowbase + lrow) * 512 + (kbase >> 2) + lkq];
    bR1 = B4[(size_t)(rowbase + lrow + 64) * 512 + (kbase >> 2) + lkq];
    {
        float av0[4] = {aR0.x, aR0.y, aR0.z, aR0.w};
        float av1[4] = {aR1.x, aR1.y, aR1.z, aR1.w};
        float bv0[4] = {bR0.x, bR0.y, bR0.z, bR0.w};
        float bv1[4] = {bR1.x, bR1.y, bR1.z, bR1.w};
#pragma unroll
        for (int i = 0; i < 4; ++i) {
            As[0][(lkq * 4 + i) * LDA_S + lrow]      = av0[i];
            As[0][(lkq * 4 + i) * LDA_S + lrow + 64] = av1[i];
            Bs[0][(lkq * 4 + i) * LDB_S + lrow]      = bv0[i];
            Bs[0][(lkq * 4 + i) * LDB_S + lrow + 64] = bv1[i];
        }
    }
    __syncthreads();

    const int NSTAGE = KSPL / BK;   // 16
    int cur = 0;
#pragma unroll 1
    for (int s = 0; s < NSTAGE; ++s) {
        // issue next stage's global loads early (register prefetch)
        if (s + 1 < NSTAGE) {
            int kofs = (s + 1) * BK;
            aR0 = A4[(size_t)lrow * 256 + ((acol0 + kofs) >> 2) + lkq];
            aR1 = A4[(size_t)(lrow + 64) * 256 + ((acol0 + kofs) >> 2) + lkq];
            bR0 = B4[(size_t)(rowbase + lrow) * 512 + ((kbase + kofs) >> 2) + lkq];
            bR1 = B4[(size_t)(rowbase + lrow + 64) * 512 + ((kbase + kofs) >> 2) + lkq];
        }
        // compute on current buffer
#pragma unroll
        for (int k = 0; k < BK; ++k) {
            const float* Arow = &As[cur][k * LDA_S];
            const float* Brow = &Bs[cur][k * LDB_S];
            float4 a0 = *(const float4*)(Arow + ty * 4);
            float4 a1 = *(const float4*)(Arow + ty * 4 + 64);
            const ull* B2 = (const ull*)Brow;
            ull bd0 = B2[tx * 2];
            ull bd1 = B2[tx * 2 + 1];
            ull bd2 = B2[tx * 2 + 32];
            ull bd3 = B2[tx * 2 + 33];
            float am[8] = {a0.x, a0.y, a0.z, a0.w, a1.x, a1.y, a1.z, a1.w};
#pragma unroll
            for (int i = 0; i < 8; ++i) {
                ull ad = pack2(am[i], am[i]);
                acc[i][0] = ffma2(ad, bd0, acc[i][0]);
                acc[i][1] = ffma2(ad, bd1, acc[i][1]);
                acc[i][2] = ffma2(ad, bd2, acc[i][2]);
                acc[i][3] = ffma2(ad, bd3, acc[i][3]);
            }
        }
        // stash prefetched tile into the other buffer
        if (s + 1 < NSTAGE) {
            int nxt = cur ^ 1;
            float av0[4] = {aR0.x, aR0.y, aR0.z, aR0.w};
            float av1[4] = {aR1.x, aR1.y, aR1.z, aR1.w};
            float bv0[4] = {bR0.x, bR0.y, bR0.z, bR0.w};
            float bv1[4] = {bR1.x, bR1.y, bR1.z, bR1.w};
#pragma unroll
            for (int i = 0; i < 4; ++i) {
                As[nxt][(lkq * 4 + i) * LDA_S + lrow]      = av0[i];
                As[nxt][(lkq * 4 + i) * LDA_S + lrow + 64] = av1[i];
                Bs[nxt][(lkq * 4 + i) * LDB_S + lrow]      = bv0[i];
                Bs[nxt][(lkq * 4 + i) * LDB_S + lrow + 64] = bv1[i];
            }
        }
        __syncthreads();
        cur ^= 1;
    }

    // epilogue: write partials (overwrite each step; no atomics -> deterministic)
    float* zp = g_zpart + (size_t)ks * B_ * N4_;
    const int ncol0 = ntile * BN + tx * 4;
#pragma unroll
    for (int i = 0; i < 8; ++i) {
        int m = (i < 4) ? (ty * 4 + i) : (ty * 4 + i - 4 + 64);
        float* dst = zp + (size_t)m * N4_ + ncol0;
        *(ulonglong2*)(dst)      = make_ulonglong2(acc[i][0], acc[i][1]);
        *(ulonglong2*)(dst + 64) = make_ulonglong2(acc[i][2], acc[i][3]);
    }
}

// ---------------- per-step elementwise: reduce splits + gates + state update ----------------
__global__ void eltwise_step(
    const float* __restrict__ bg, const float* __restrict__ bi,
    const float* __restrict__ bf, const float* __restrict__ bo,
    float* __restrict__ out, int t)
{
    int idx = blockIdx.x * blockDim.x + threadIdx.x;   // 0 .. B*H-1
    int u = idx & (H_ - 1);
    int b = idx >> 10;

    float zg = bg[u], zi = bi[u], zf = bf[u], zo = bo[u];
#pragma unroll
    for (int s = 0; s < NSPLIT; ++s) {
        const float* zp = g_zpart + ((size_t)s * B_ + b) * N4_;
        zg += zp[u];
        zi += zp[u + 1024];
        zf += zp[u + 2048];
        zo += zp[u + 3072];
    }
    float g  = tanhf(zg);
    float ii = 1.0f / (1.0f + expf(-zi));
    float f  = 1.0f / (1.0f + expf(-zf));
    float o  = 1.0f / (1.0f + expf(-zo));

    float c = f * g_c[idx] + ii * g;
    g_c[idx] = c;
    out[(size_t)t * B_ * H_ + idx] = o * tanhf(c);
}

// ---------------- launch ----------------
extern "C" void kernel_launch(void* const* d_in, const int* in_sizes, int n_in,
                              void* d_out, int out_size)
{
    const float* embeds = (const float*)d_in[0];
    const float* Wg = (const float*)d_in[1];
    const float* Wi = (const float*)d_in[2];
    const float* Wf = (const float*)d_in[3];
    const float* Wo = (const float*)d_in[4];
    const float* bg = (const float*)d_in[5];
    const float* bi = (const float*)d_in[6];
    const float* bf = (const float*)d_in[7];
    const float* bo = (const float*)d_in[8];
    float* out = (float*)d_out;

    init_kernel<<<(B_ * H_ + 255) / 256, 256>>>(out);
    for (int t = 1; t < T_; ++t) {
        gemm_step<<<dim3(32, 8), 256>>>(embeds, Wg, Wi, Wf, Wo, out, t);
        eltwise_step<<<(B_ * H_ + 255) / 256, 256>>>(bg, bi, bf, bo, out, t);
    }
}

// round 4
// speedup vs baseline: 2.2108x; 2.2108x over previous
#include <cuda_runtime.h>
#include <cuda_bf16.h>
#include <cstdint>

// ---------------- problem constants ----------------
#define T_    256
#define B_    128
#define E_    1024
#define H_    1024
#define N4_   4096
#define BH_   (B_ * H_)
#define NSPLIT 4            // K-splits for the per-step h-GEMM

// ---------------- static device scratch ----------------
__device__ float          g_zx[(size_t)T_ * B_ * N4_];   // x-part preactivations, all t
__device__ float          g_zh[NSPLIT * B_ * N4_];       // per-step h-part partials
__device__ float          g_c[BH_];                      // cell state
__device__ __nv_bfloat16  g_eh[(size_t)T_ * B_ * E_];    // embeds hi
__device__ __nv_bfloat16  g_el[(size_t)T_ * B_ * E_];    // embeds lo
__device__ __nv_bfloat16  g_wxh[N4_ * 1024];             // Wx hi (gate-concat rows, K-major)
__device__ __nv_bfloat16  g_wxl[N4_ * 1024];
__device__ __nv_bfloat16  g_whh[N4_ * 1024];             // Wh hi
__device__ __nv_bfloat16  g_whl[N4_ * 1024];
__device__ __nv_bfloat16  g_hhi[BH_];                    // h_{t-1} hi
__device__ __nv_bfloat16  g_hlo[BH_];                    // h_{t-1} lo

// ---------------- arch-generic PTX helpers ----------------
__device__ __forceinline__ uint32_t smem_u32(const void* p) {
    uint32_t a;
    asm("{ .reg .u64 t; cvta.to.shared.u64 t, %1; cvt.u32.u64 %0, t; }" : "=r"(a) : "l"(p));
    return a;
}
__device__ __forceinline__ void ldsm4(uint32_t r[4], uint32_t saddr) {
    asm volatile("ldmatrix.sync.aligned.m8n8.x4.shared.b16 {%0,%1,%2,%3}, [%4];"
                 : "=r"(r[0]), "=r"(r[1]), "=r"(r[2]), "=r"(r[3]) : "r"(saddr));
}
__device__ __forceinline__ void mma16816(float c[4], const uint32_t a[4],
                                         uint32_t b0, uint32_t b1) {
    asm volatile("mma.sync.aligned.m16n8k16.row.col.f32.bf16.bf16.f32 "
                 "{%0,%1,%2,%3}, {%4,%5,%6,%7}, {%8,%9}, {%0,%1,%2,%3};"
                 : "+f"(c[0]), "+f"(c[1]), "+f"(c[2]), "+f"(c[3])
                 : "r"(a[0]), "r"(a[1]), "r"(a[2]), "r"(a[3]), "r"(b0), "r"(b1));
}
#define CP_ASYNC16(dst, src) \
    asm volatile("cp.async.cg.shared.global [%0], [%1], 16;" :: "r"(dst), "l"(src))
#define CP_COMMIT() asm volatile("cp.async.commit_group;" ::: "memory")
#define CP_WAIT1()  asm volatile("cp.async.wait_group 1;" ::: "memory")
#define CP_WAIT0()  asm volatile("cp.async.wait_group 0;" ::: "memory")

// ---------------- 3-plane bf16 GEMM (mma.sync): C[128m x 128n] = A @ B^T ----------------
// A planes: (M,1024) bf16 row-major; B planes: (4096,1024) bf16 row-major (B^T layout).
// grid = (ntiles, mtiles, ksplits); split kz covers K range [kz*klen, kz*klen+klen).
// Stage = K64 slab: 4 tiles (Ah, Al, Bh, Bl), each 128 rows x 128B, XOR-swizzled.
__global__ __launch_bounds__(256, 1)
void gemm_mma(const __nv_bfloat16* __restrict__ Ah, const __nv_bfloat16* __restrict__ Al,
              int lda,
              const __nv_bfloat16* __restrict__ Bh, const __nv_bfloat16* __restrict__ Bl,
              float* __restrict__ C, size_t csplit_stride, int klen)
{
    extern __shared__ __align__(128) char sm[];

    const int tid  = threadIdx.x;
    const int lane = tid & 31;
    const int wid  = tid >> 5;
    const int wm   = wid & 1;        // 2 warp-rows   (64 m each)
    const int wn   = wid >> 1;       // 4 warp-cols   (32 n each)
    const int nt = blockIdx.x, mt = blockIdx.y, kz = blockIdx.z;
    const int kofs = kz * klen;
    const int nstages = klen >> 6;

    const __nv_bfloat16* a_h = Ah + (size_t)mt * 128 * lda + kofs;
    const __nv_bfloat16* a_l = Al + (size_t)mt * 128 * lda + kofs;
    const __nv_bfloat16* b_h = Bh + (size_t)nt * 128 * 1024 + kofs;
    const __nv_bfloat16* b_l = Bl + (size_t)nt * 128 * 1024 + kofs;

    // stage loader mapping: 256 threads; each copies 16 chunks of 16B
    const int lrow = tid >> 3;       // 0..31
    const int lc   = tid & 7;        // 16B chunk in 128B row

#define LOAD_STAGE(buf, s) do {                                                    \
        char* dst_ = sm + (buf) * 65536;                                           \
        const __nv_bfloat16* s0_ = a_h + (s) * 64;                                 \
        const __nv_bfloat16* s1_ = a_l + (s) * 64;                                 \
        const __nv_bfloat16* s2_ = b_h + (s) * 64;                                 \
        const __nv_bfloat16* s3_ = b_l + (s) * 64;                                 \
        _Pragma("unroll")                                                          \
        for (int p = 0; p < 4; ++p) {                                              \
            int row = lrow + p * 32;                                               \
            uint32_t so = row * 128 + ((lc ^ (row & 7)) << 4);                     \
            CP_ASYNC16(smem_u32(dst_ + 0     + so), s0_ + (size_t)row * lda + lc * 8); \
            CP_ASYNC16(smem_u32(dst_ + 16384 + so), s1_ + (size_t)row * lda + lc * 8); \
            CP_ASYNC16(smem_u32(dst_ + 32768 + so), s2_ + (size_t)row * 1024 + lc * 8); \
            CP_ASYNC16(smem_u32(dst_ + 49152 + so), s3_ + (size_t)row * 1024 + lc * 8); \
        }                                                                          \
        CP_COMMIT();                                                               \
    } while (0)

    float cacc[4][4][4];
#pragma unroll
    for (int mi = 0; mi < 4; ++mi)
#pragma unroll
        for (int ni = 0; ni < 4; ++ni)
#pragma unroll
            for (int q = 0; q < 4; ++q) cacc[mi][ni][q] = 0.0f;

    // prologue: prefetch stages 0 and 1
    LOAD_STAGE(0, 0);
    if (nstages > 1) LOAD_STAGE(1, 1);

#pragma unroll 1
    for (int s = 0; s < nstages; ++s) {
        if (s + 1 < nstages) { CP_WAIT1(); } else { CP_WAIT0(); }
        __syncthreads();

        const char* base = sm + (s & 1) * 65536;
#pragma unroll
        for (int j = 0; j < 4; ++j) {             // k16 sub-steps within K64 slab
            uint32_t aH[4][4], aL[4][4], bH[2][4], bL[2][4];
#pragma unroll
            for (int mi = 0; mi < 4; ++mi) {
                int row = wm * 64 + mi * 16 + (lane & 15);
                int ch  = 2 * j + (lane >> 4);
                uint32_t off = row * 128 + ((ch ^ (row & 7)) << 4);
                ldsm4(aH[mi], smem_u32(base + 0     + off));
                ldsm4(aL[mi], smem_u32(base + 16384 + off));
            }
#pragma unroll
            for (int pi = 0; pi < 2; ++pi) {      // each covers two n8 tiles
                int row = wn * 32 + pi * 16 + (lane & 7) + ((lane & 16) >> 1);
                int ch  = 2 * j + ((lane >> 3) & 1);
                uint32_t off = row * 128 + ((ch ^ (row & 7)) << 4);
                ldsm4(bH[pi], smem_u32(base + 32768 + off));
                ldsm4(bL[pi], smem_u32(base + 49152 + off));
            }
#pragma unroll
            for (int mi = 0; mi < 4; ++mi)
#pragma unroll
                for (int ni = 0; ni < 4; ++ni) {
                    uint32_t bh0 = bH[ni >> 1][(ni & 1) * 2];
                    uint32_t bh1 = bH[ni >> 1][(ni & 1) * 2 + 1];
                    uint32_t bl0 = bL[ni >> 1][(ni & 1) * 2];
                    uint32_t bl1 = bL[ni >> 1][(ni & 1) * 2 + 1];
                    mma16816(cacc[mi][ni], aH[mi], bh0, bh1);   // Ah*Bh
                    mma16816(cacc[mi][ni], aH[mi], bl0, bl1);   // Ah*Bl
                    mma16816(cacc[mi][ni], aL[mi], bh0, bh1);   // Al*Bh
                }
        }
        __syncthreads();
        if (s + 2 < nstages) LOAD_STAGE(s & 1, s + 2);
    }

    // epilogue: fragment -> gmem (float2 stores)
    float* cb = C + (size_t)kz * csplit_stride + (size_t)mt * 128 * N4_ + nt * 128;
#pragma unroll
    for (int mi = 0; mi < 4; ++mi)
#pragma unroll
        for (int ni = 0; ni < 4; ++ni) {
            int r   = wm * 64 + mi * 16 + (lane >> 2);
            int col = wn * 32 + ni * 8 + (lane & 3) * 2;
            *(float2*)(cb + (size_t)r * N4_ + col) =
                make_float2(cacc[mi][ni][0], cacc[mi][ni][1]);
            *(float2*)(cb + (size_t)(r + 8) * N4_ + col) =
                make_float2(cacc[mi][ni][2], cacc[mi][ni][3]);
        }
#undef LOAD_STAGE
}

// ---------------- prep kernels ----------------
__global__ void split_plane(const float* __restrict__ src, __nv_bfloat16* __restrict__ hi,
                            __nv_bfloat16* __restrict__ lo, int n) {
    int i = blockIdx.x * blockDim.x + threadIdx.x;
    if (i < n) {
        float v = src[i];
        __nv_bfloat16 h = __float2bfloat16(v);
        hi[i] = h;
        lo[i] = __float2bfloat16(v - __bfloat162float(h));
    }
}

__global__ void split_W(const float* __restrict__ Wg, const float* __restrict__ Wi,
                        const float* __restrict__ Wf, const float* __restrict__ Wo) {
    int idx = blockIdx.x * blockDim.x + threadIdx.x;   // 0 .. 4*1024*2048-1
    if (idx >= 4 * 1024 * 2048) return;
    int gate = idx >> 21;
    int rem  = idx & ((1 << 21) - 1);
    int n    = rem >> 11;
    int k    = rem & 2047;
    const float* W = (gate == 0) ? Wg : (gate == 1) ? Wi : (gate == 2) ? Wf : Wo;
    float v = W[(size_t)n * 2048 + k];
    __nv_bfloat16 h = __float2bfloat16(v);
    __nv_bfloat16 l = __float2bfloat16(v - __bfloat162float(h));
    int gr = gate * 1024 + n;
    if (k < 1024) {
        g_wxh[(size_t)gr * 1024 + k] = h;
        g_wxl[(size_t)gr * 1024 + k] = l;
    } else {
        g_whh[(size_t)gr * 1024 + (k - 1024)] = h;
        g_whl[(size_t)gr * 1024 + (k - 1024)] = l;
    }
}

__global__ void init_state(float* __restrict__ out) {
    int i = blockIdx.x * blockDim.x + threadIdx.x;
    if (i < BH_) {
        out[i] = 0.0f;              // output[0] = h0 = 0
        g_c[i] = 0.0f;
        g_hhi[i] = __float2bfloat16(0.0f);
        g_hlo[i] = __float2bfloat16(0.0f);
    }
}

// ---------------- per-step elementwise ----------------
__global__ void eltwise_step(const float* __restrict__ bg, const float* __restrict__ bi,
                             const float* __restrict__ bf, const float* __restrict__ bo,
                             float* __restrict__ out, int t) {
    int idx = blockIdx.x * blockDim.x + threadIdx.x;
    int u = idx & (H_ - 1);
    int b = idx >> 10;

    const float* zx = g_zx + ((size_t)t * B_ + b) * N4_;

    float zg = zx[u]        + bg[u];
    float zi = zx[u + 1024] + bi[u];
    float zf = zx[u + 2048] + bf[u];
    float zo = zx[u + 3072] + bo[u];
#pragma unroll
    for (int s = 0; s < NSPLIT; ++s) {
        const float* zh = g_zh + ((size_t)s * B_ + b) * N4_;
        zg += zh[u];
        zi += zh[u + 1024];
        zf += zh[u + 2048];
        zo += zh[u + 3072];
    }

    float g  = tanhf(zg);
    float ii = 1.0f / (1.0f + expf(-zi));
    float f  = 1.0f / (1.0f + expf(-zf));
    float o  = 1.0f / (1.0f + expf(-zo));

    float c = f * g_c[idx] + ii * g;
    g_c[idx] = c;
    float h = o * tanhf(c);
    out[(size_t)t * BH_ + idx] = h;
    __nv_bfloat16 hh = __float2bfloat16(h);
    g_hhi[idx] = hh;
    g_hlo[idx] = __float2bfloat16(h - __bfloat162float(hh));
}

// ---------------- launch ----------------
#define GEMM_SMEM (2 * 65536)

extern "C" void kernel_launch(void* const* d_in, const int* in_sizes, int n_in,
                              void* d_out, int out_size)
{
    const float* embeds = (const float*)d_in[0];
    const float* Wg = (const float*)d_in[1];
    const float* Wi = (const float*)d_in[2];
    const float* Wf = (const float*)d_in[3];
    const float* Wo = (const float*)d_in[4];
    const float* bg = (const float*)d_in[5];
    const float* bi = (const float*)d_in[6];
    const float* bf = (const float*)d_in[7];
    const float* bo = (const float*)d_in[8];
    float* out = (float*)d_out;

    cudaFuncSetAttribute(gemm_mma, cudaFuncAttributeMaxDynamicSharedMemorySize, GEMM_SMEM);

    __nv_bfloat16 *p_eh, *p_el, *p_wxh, *p_wxl, *p_whh, *p_whl, *p_hhi, *p_hlo;
    float *p_zx, *p_zh;
    cudaGetSymbolAddress((void**)&p_eh,  g_eh);
    cudaGetSymbolAddress((void**)&p_el,  g_el);
    cudaGetSymbolAddress((void**)&p_wxh, g_wxh);
    cudaGetSymbolAddress((void**)&p_wxl, g_wxl);
    cudaGetSymbolAddress((void**)&p_whh, g_whh);
    cudaGetSymbolAddress((void**)&p_whl, g_whl);
    cudaGetSymbolAddress((void**)&p_hhi, g_hhi);
    cudaGetSymbolAddress((void**)&p_hlo, g_hlo);
    cudaGetSymbolAddress((void**)&p_zx,  g_zx);
    cudaGetSymbolAddress((void**)&p_zh,  g_zh);

    // prep
    {
        int n = T_ * B_ * E_;
        split_plane<<<(n + 255) / 256, 256>>>(embeds, p_eh, p_el, n);
    }
    split_W<<<(4 * 1024 * 2048 + 255) / 256, 256>>>(Wg, Wi, Wf, Wo);
    init_state<<<(BH_ + 255) / 256, 256>>>(out);

    // batch: Zx[t] = x_t @ Wx^T for all t (M = 32768 rows, K = 1024)
    gemm_mma<<<dim3(32, 256, 1), 256, GEMM_SMEM>>>(p_eh, p_el, 1024, p_wxh, p_wxl,
                                                   p_zx, 0, 1024);

    // recurrence: per-step h @ Wh^T (M = 128, K = 1024 split 4 ways)
    for (int t = 1; t < T_; ++t) {
        gemm_mma<<<dim3(32, 1, NSPLIT), 256, GEMM_SMEM>>>(p_hhi, p_hlo, 1024, p_whh, p_whl,
                                                          p_zh, (size_t)B_ * N4_, 1024 / NSPLIT);
        eltwise_step<<<(BH_ + 255) / 256, 256>>>(bg, bi, bf, bo, out, t);
    }
}

// round 5
// speedup vs baseline: 2.2206x; 1.0044x over previous
#include <cuda_runtime.h>
#include <cuda_bf16.h>
#include <cstdint>

// ---------------- problem constants ----------------
#define T_    256
#define B_    128
#define E_    1024
#define H_    1024
#define N4_   4096
#define BH_   (B_ * H_)
#define NSPLIT 4            // K-splits for the per-step h-GEMM

// ---------------- static device scratch ----------------
__device__ float          g_zx[(size_t)T_ * B_ * N4_];   // x-part preactivations, all t
__device__ float          g_zh[NSPLIT * B_ * N4_];       // per-step h-part partials
__device__ float          g_c[BH_];                      // cell state
__device__ __nv_bfloat16  g_eh[(size_t)T_ * B_ * E_];    // embeds hi
__device__ __nv_bfloat16  g_el[(size_t)T_ * B_ * E_];    // embeds lo
__device__ __nv_bfloat16  g_wxh[N4_ * 1024];             // Wx hi (gate-concat rows, K-major)
__device__ __nv_bfloat16  g_wxl[N4_ * 1024];
__device__ __nv_bfloat16  g_whh[N4_ * 1024];             // Wh hi
__device__ __nv_bfloat16  g_whl[N4_ * 1024];
__device__ __nv_bfloat16  g_hhi[BH_];                    // h_{t-1} hi
__device__ __nv_bfloat16  g_hlo[BH_];                    // h_{t-1} lo
__device__ unsigned       g_barrier_cnt;                 // persistent-kernel grid barrier

// ---------------- arch-generic PTX helpers ----------------
__device__ __forceinline__ uint32_t smem_u32(const void* p) {
    uint32_t a;
    asm("{ .reg .u64 t; cvta.to.shared.u64 t, %1; cvt.u32.u64 %0, t; }" : "=r"(a) : "l"(p));
    return a;
}
__device__ __forceinline__ void ldsm4(uint32_t r[4], uint32_t saddr) {
    asm volatile("ldmatrix.sync.aligned.m8n8.x4.shared.b16 {%0,%1,%2,%3}, [%4];"
                 : "=r"(r[0]), "=r"(r[1]), "=r"(r[2]), "=r"(r[3]) : "r"(saddr));
}
__device__ __forceinline__ void mma16816(float c[4], const uint32_t a[4],
                                         uint32_t b0, uint32_t b1) {
    asm volatile("mma.sync.aligned.m16n8k16.row.col.f32.bf16.bf16.f32 "
                 "{%0,%1,%2,%3}, {%4,%5,%6,%7}, {%8,%9}, {%0,%1,%2,%3};"
                 : "+f"(c[0]), "+f"(c[1]), "+f"(c[2]), "+f"(c[3])
                 : "r"(a[0]), "r"(a[1]), "r"(a[2]), "r"(a[3]), "r"(b0), "r"(b1));
}
#define CP_ASYNC16(dst, src) \
    asm volatile("cp.async.cg.shared.global [%0], [%1], 16;" :: "r"(dst), "l"(src))
#define CP_COMMIT() asm volatile("cp.async.commit_group;" ::: "memory")
#define CP_WAIT1()  asm volatile("cp.async.wait_group 1;" ::: "memory")
#define CP_WAIT0()  asm volatile("cp.async.wait_group 0;" ::: "memory")

// ---------------- grid barrier (all CTAs co-resident; CG grid.sync pattern) ----------------
__device__ __forceinline__ void grid_barrier(unsigned target) {
    __syncthreads();
    if (threadIdx.x == 0) {
        __threadfence();
        atomicAdd(&g_barrier_cnt, 1u);
        while (*(volatile unsigned*)&g_barrier_cnt < target) { }
        __threadfence();
    }
    __syncthreads();
}

// ---------------- batch 3-plane bf16 GEMM (unchanged, known-good) ----------------
__global__ __launch_bounds__(256, 1)
void gemm_mma(const __nv_bfloat16* __restrict__ Ah, const __nv_bfloat16* __restrict__ Al,
              int lda,
              const __nv_bfloat16* __restrict__ Bh, const __nv_bfloat16* __restrict__ Bl,
              float* __restrict__ C, size_t csplit_stride, int klen)
{
    extern __shared__ __align__(128) char sm[];

    const int tid  = threadIdx.x;
    const int lane = tid & 31;
    const int wid  = tid >> 5;
    const int wm   = wid & 1;
    const int wn   = wid >> 1;
    const int nt = blockIdx.x, mt = blockIdx.y, kz = blockIdx.z;
    const int kofs = kz * klen;
    const int nstages = klen >> 6;

    const __nv_bfloat16* a_h = Ah + (size_t)mt * 128 * lda + kofs;
    const __nv_bfloat16* a_l = Al + (size_t)mt * 128 * lda + kofs;
    const __nv_bfloat16* b_h = Bh + (size_t)nt * 128 * 1024 + kofs;
    const __nv_bfloat16* b_l = Bl + (size_t)nt * 128 * 1024 + kofs;

    const int lrow = tid >> 3;
    const int lc   = tid & 7;

#define LOAD_STAGE(buf, s) do {                                                    \
        char* dst_ = sm + (buf) * 65536;                                           \
        const __nv_bfloat16* s0_ = a_h + (s) * 64;                                 \
        const __nv_bfloat16* s1_ = a_l + (s) * 64;                                 \
        const __nv_bfloat16* s2_ = b_h + (s) * 64;                                 \
        const __nv_bfloat16* s3_ = b_l + (s) * 64;                                 \
        _Pragma("unroll")                                                          \
        for (int p = 0; p < 4; ++p) {                                              \
            int row = lrow + p * 32;                                               \
            uint32_t so = row * 128 + ((lc ^ (row & 7)) << 4);                     \
            CP_ASYNC16(smem_u32(dst_ + 0     + so), s0_ + (size_t)row * lda + lc * 8); \
            CP_ASYNC16(smem_u32(dst_ + 16384 + so), s1_ + (size_t)row * lda + lc * 8); \
            CP_ASYNC16(smem_u32(dst_ + 32768 + so), s2_ + (size_t)row * 1024 + lc * 8); \
            CP_ASYNC16(smem_u32(dst_ + 49152 + so), s3_ + (size_t)row * 1024 + lc * 8); \
        }                                                                          \
        CP_COMMIT();                                                               \
    } while (0)

    float cacc[4][4][4];
#pragma unroll
    for (int mi = 0; mi < 4; ++mi)
#pragma unroll
        for (int ni = 0; ni < 4; ++ni)
#pragma unroll
            for (int q = 0; q < 4; ++q) cacc[mi][ni][q] = 0.0f;

    LOAD_STAGE(0, 0);
    if (nstages > 1) LOAD_STAGE(1, 1);

#pragma unroll 1
    for (int s = 0; s < nstages; ++s) {
        if (s + 1 < nstages) { CP_WAIT1(); } else { CP_WAIT0(); }
        __syncthreads();

        const char* base = sm + (s & 1) * 65536;
#pragma unroll
        for (int j = 0; j < 4; ++j) {
            uint32_t aH[4][4], aL[4][4], bH[2][4], bL[2][4];
#pragma unroll
            for (int mi = 0; mi < 4; ++mi) {
                int row = wm * 64 + mi * 16 + (lane & 15);
                int ch  = 2 * j + (lane >> 4);
                uint32_t off = row * 128 + ((ch ^ (row & 7)) << 4);
                ldsm4(aH[mi], smem_u32(base + 0     + off));
                ldsm4(aL[mi], smem_u32(base + 16384 + off));
            }
#pragma unroll
            for (int pi = 0; pi < 2; ++pi) {
                int row = wn * 32 + pi * 16 + (lane & 7) + ((lane & 16) >> 1);
                int ch  = 2 * j + ((lane >> 3) & 1);
                uint32_t off = row * 128 + ((ch ^ (row & 7)) << 4);
                ldsm4(bH[pi], smem_u32(base + 32768 + off));
                ldsm4(bL[pi], smem_u32(base + 49152 + off));
            }
#pragma unroll
            for (int mi = 0; mi < 4; ++mi)
#pragma unroll
                for (int ni = 0; ni < 4; ++ni) {
                    uint32_t bh0 = bH[ni >> 1][(ni & 1) * 2];
                    uint32_t bh1 = bH[ni >> 1][(ni & 1) * 2 + 1];
                    uint32_t bl0 = bL[ni >> 1][(ni & 1) * 2];
                    uint32_t bl1 = bL[ni >> 1][(ni & 1) * 2 + 1];
                    mma16816(cacc[mi][ni], aH[mi], bh0, bh1);
                    mma16816(cacc[mi][ni], aH[mi], bl0, bl1);
                    mma16816(cacc[mi][ni], aL[mi], bh0, bh1);
                }
        }
        __syncthreads();
        if (s + 2 < nstages) LOAD_STAGE(s & 1, s + 2);
    }

    float* cb = C + (size_t)kz * csplit_stride + (size_t)mt * 128 * N4_ + nt * 128;
#pragma unroll
    for (int mi = 0; mi < 4; ++mi)
#pragma unroll
        for (int ni = 0; ni < 4; ++ni) {
            int r   = wm * 64 + mi * 16 + (lane >> 2);
            int col = wn * 32 + ni * 8 + (lane & 3) * 2;
            *(float2*)(cb + (size_t)r * N4_ + col) =
                make_float2(cacc[mi][ni][0], cacc[mi][ni][1]);
            *(float2*)(cb + (size_t)(r + 8) * N4_ + col) =
                make_float2(cacc[mi][ni][2], cacc[mi][ni][3]);
        }
#undef LOAD_STAGE
}

// ---------------- persistent recurrence kernel ----------------
// 128 CTAs (1/SM, all co-resident). CTA = (nt 0..31, kz 0..3).
// smem: [0,64K)   Wh-hi sub-slabs s=0..3 (16KB each, swizzled 128x128B tiles)
//       [64K,128K) Wh-lo sub-slabs
//       [128K,192K) h double buffer: buf b at 128K+b*32K (hi +0, lo +16K)
#define PK_CTAS  128
#define PK_SMEM  196608
#define SM_WHI(s)    (sm + (s) * 16384)
#define SM_WLO(s)    (sm + 65536 + (s) * 16384)
#define SM_HBUF(b)   (sm + 131072 + (b) * 32768)

__global__ __launch_bounds__(256, 1)
void lstm_persistent(const float* __restrict__ bg, const float* __restrict__ bi,
                     const float* __restrict__ bf, const float* __restrict__ bo,
                     float* __restrict__ out)
{
    extern __shared__ __align__(128) char sm[];

    const int tid  = threadIdx.x;
    const int lane = tid & 31;
    const int wid  = tid >> 5;
    const int wm   = wid & 1;
    const int wn   = wid >> 1;
    const int cta  = blockIdx.x;
    const int nt   = cta & 31;
    const int kz   = cta >> 5;

    const int lrow = tid >> 3;
    const int lc   = tid & 7;

    // ---- load resident W slab (hi+lo, 4 K64 sub-slabs) : one cp.async group ----
#pragma unroll
    for (int sub = 0; sub < 4; ++sub) {
#pragma unroll
        for (int p = 0; p < 4; ++p) {
            int row = lrow + p * 32;
            uint32_t so = row * 128 + ((lc ^ (row & 7)) << 4);
            size_t gofs = (size_t)(nt * 128 + row) * 1024 + kz * 256 + sub * 64 + lc * 8;
            CP_ASYNC16(smem_u32(SM_WHI(sub) + so), g_whh + gofs);
            CP_ASYNC16(smem_u32(SM_WLO(sub) + so), g_whl + gofs);
        }
    }
    CP_COMMIT();

#define LOADH(buf, s) do {                                                          \
        char* dst_ = SM_HBUF(buf);                                                  \
        _Pragma("unroll")                                                           \
        for (int p = 0; p < 4; ++p) {                                               \
            int row = lrow + p * 32;                                                \
            uint32_t so = row * 128 + ((lc ^ (row & 7)) << 4);                      \
            size_t go = (size_t)row * 1024 + kz * 256 + (s) * 64 + lc * 8;          \
            CP_ASYNC16(smem_u32(dst_ + so),         g_hhi + go);                    \
            CP_ASYNC16(smem_u32(dst_ + 16384 + so), g_hlo + go);                    \
        }                                                                           \
        CP_COMMIT();                                                                \
    } while (0)

    unsigned nbar = 0;

#pragma unroll 1
    for (int t = 1; t < T_; ++t) {
        // h_{t-1} (hi/lo planes) visible to all CTAs
        grid_barrier(++nbar * PK_CTAS);

        LOADH(0, 0);
        LOADH(1, 1);

        float cacc[4][4][4];
#pragma unroll
        for (int mi = 0; mi < 4; ++mi)
#pragma unroll
            for (int ni = 0; ni < 4; ++ni)
#pragma unroll
                for (int q = 0; q < 4; ++q) cacc[mi][ni][q] = 0.0f;

#pragma unroll 1
        for (int s = 0; s < 4; ++s) {
            if (s + 1 < 4) { CP_WAIT1(); } else { CP_WAIT0(); }
            __syncthreads();

            const char* abase  = SM_HBUF(s & 1);
            const char* bhbase = SM_WHI(s);
            const char* blbase = SM_WLO(s);
#pragma unroll
            for (int j = 0; j < 4; ++j) {
                uint32_t aH[4][4], aL[4][4], bH[2][4], bL[2][4];
#pragma unroll
                for (int mi = 0; mi < 4; ++mi) {
                    int row = wm * 64 + mi * 16 + (lane & 15);
                    int ch  = 2 * j + (lane >> 4);
                    uint32_t off = row * 128 + ((ch ^ (row & 7)) << 4);
                    ldsm4(aH[mi], smem_u32(abase + off));
                    ldsm4(aL[mi], smem_u32(abase + 16384 + off));
                }
#pragma unroll
                for (int pi = 0; pi < 2; ++pi) {
                    int row = wn * 32 + pi * 16 + (lane & 7) + ((lane & 16) >> 1);
                    int ch  = 2 * j + ((lane >> 3) & 1);
                    uint32_t off = row * 128 + ((ch ^ (row & 7)) << 4);
                    ldsm4(bH[pi], smem_u32(bhbase + off));
                    ldsm4(bL[pi], smem_u32(blbase + off));
                }
#pragma unroll
                for (int mi = 0; mi < 4; ++mi)
#pragma unroll
                    for (int ni = 0; ni < 4; ++ni) {
                        uint32_t bh0 = bH[ni >> 1][(ni & 1) * 2];
                        uint32_t bh1 = bH[ni >> 1][(ni & 1) * 2 + 1];
                        uint32_t bl0 = bL[ni >> 1][(ni & 1) * 2];
                        uint32_t bl1 = bL[ni >> 1][(ni & 1) * 2 + 1];
                        mma16816(cacc[mi][ni], aH[mi], bh0, bh1);
                        mma16816(cacc[mi][ni], aH[mi], bl0, bl1);
                        mma16816(cacc[mi][ni], aL[mi], bh0, bh1);
                    }
            }
            __syncthreads();
            if (s + 2 < 4) LOADH(s & 1, s + 2);
        }

        // write z partials for this (nt, kz)
        {
            float* cb = g_zh + (size_t)kz * (B_ * N4_) + nt * 128;
#pragma unroll
            for (int mi = 0; mi < 4; ++mi)
#pragma unroll
                for (int ni = 0; ni < 4; ++ni) {
                    int r   = wm * 64 + mi * 16 + (lane >> 2);
                    int col = wn * 32 + ni * 8 + (lane & 3) * 2;
                    *(float2*)(cb + (size_t)r * N4_ + col) =
                        make_float2(cacc[mi][ni][0], cacc[mi][ni][1]);
                    *(float2*)(cb + (size_t)(r + 8) * N4_ + col) =
                        make_float2(cacc[mi][ni][2], cacc[mi][ni][3]);
                }
        }

        // all partials visible
        grid_barrier(++nbar * PK_CTAS);

        // ---- eltwise phase: CTA b = cta handles batch row, 4 elements/thread ----
        {
            const int b  = cta;
            const int u0 = tid * 4;
            const float* zx = g_zx + ((size_t)t * B_ + b) * N4_;

            float4 zg = *(const float4*)(zx + u0);
            float4 zi = *(const float4*)(zx + u0 + 1024);
            float4 zf = *(const float4*)(zx + u0 + 2048);
            float4 zo = *(const float4*)(zx + u0 + 3072);
#pragma unroll
            for (int s = 0; s < NSPLIT; ++s) {
                const float* zh = g_zh + ((size_t)s * B_ + b) * N4_;
                float4 a = *(const float4*)(zh + u0);
                float4 c2 = *(const float4*)(zh + u0 + 1024);
                float4 d = *(const float4*)(zh + u0 + 2048);
                float4 e = *(const float4*)(zh + u0 + 3072);
                zg.x += a.x; zg.y += a.y; zg.z += a.z; zg.w += a.w;
                zi.x += c2.x; zi.y += c2.y; zi.z += c2.z; zi.w += c2.w;
                zf.x += d.x; zf.y += d.y; zf.z += d.z; zf.w += d.w;
                zo.x += e.x; zo.y += e.y; zo.z += e.z; zo.w += e.w;
            }
            float4 vbg = *(const float4*)(bg + u0);
            float4 vbi = *(const float4*)(bi + u0);
            float4 vbf = *(const float4*)(bf + u0);
            float4 vbo = *(const float4*)(bo + u0);

            float zga[4] = {zg.x + vbg.x, zg.y + vbg.y, zg.z + vbg.z, zg.w + vbg.w};
            float zia[4] = {zi.x + vbi.x, zi.y + vbi.y, zi.z + vbi.z, zi.w + vbi.w};
            float zfa[4] = {zf.x + vbf.x, zf.y + vbf.y, zf.z + vbf.z, zf.w + vbf.w};
            float zoa[4] = {zo.x + vbo.x, zo.y + vbo.y, zo.z + vbo.z, zo.w + vbo.w};

            float4 cprev = *(float4*)(g_c + (size_t)b * 1024 + u0);
            float cp4[4] = {cprev.x, cprev.y, cprev.z, cprev.w};

            float hv[4], cv[4];
#pragma unroll
            for (int q = 0; q < 4; ++q) {
                float g  = tanhf(zga[q]);
                float ii = 1.0f / (1.0f + expf(-zia[q]));
                float f  = 1.0f / (1.0f + expf(-zfa[q]));
                float o  = 1.0f / (1.0f + expf(-zoa[q]));
                float c  = f * cp4[q] + ii * g;
                cv[q] = c;
                hv[q] = o * tanhf(c);
            }
            *(float4*)(g_c + (size_t)b * 1024 + u0) = make_float4(cv[0], cv[1], cv[2], cv[3]);
            *(float4*)(out + ((size_t)t * B_ + b) * 1024 + u0) =
                make_float4(hv[0], hv[1], hv[2], hv[3]);

            union { __nv_bfloat16 v[4]; uint2 u; } hh, hl;
#pragma unroll
            for (int q = 0; q < 4; ++q) {
                __nv_bfloat16 h = __float2bfloat16(hv[q]);
                hh.v[q] = h;
                hl.v[q] = __float2bfloat16(hv[q] - __bfloat162float(h));
            }
            *(uint2*)(g_hhi + (size_t)b * 1024 + u0) = hh.u;
            *(uint2*)(g_hlo + (size_t)b * 1024 + u0) = hl.u;
        }
    }
#undef LOADH
}

// ---------------- prep kernels ----------------
__global__ void split_plane(const float* __restrict__ src, __nv_bfloat16* __restrict__ hi,
                            __nv_bfloat16* __restrict__ lo, int n) {
    int i = blockIdx.x * blockDim.x + threadIdx.x;
    if (i < n) {
        float v = src[i];
        __nv_bfloat16 h = __float2bfloat16(v);
        hi[i] = h;
        lo[i] = __float2bfloat16(v - __bfloat162float(h));
    }
}

__global__ void split_W(const float* __restrict__ Wg, const float* __restrict__ Wi,
                        const float* __restrict__ Wf, const float* __restrict__ Wo) {
    int idx = blockIdx.x * blockDim.x + threadIdx.x;
    if (idx >= 4 * 1024 * 2048) return;
    int gate = idx >> 21;
    int rem  = idx & ((1 << 21) - 1);
    int n    = rem >> 11;
    int k    = rem & 2047;
    const float* W = (gate == 0) ? Wg : (gate == 1) ? Wi : (gate == 2) ? Wf : Wo;
    float v = W[(size_t)n * 2048 + k];
    __nv_bfloat16 h = __float2bfloat16(v);
    __nv_bfloat16 l = __float2bfloat16(v - __bfloat162float(h));
    int gr = gate * 1024 + n;
    if (k < 1024) {
        g_wxh[(size_t)gr * 1024 + k] = h;
        g_wxl[(size_t)gr * 1024 + k] = l;
    } else {
        g_whh[(size_t)gr * 1024 + (k - 1024)] = h;
        g_whl[(size_t)gr * 1024 + (k - 1024)] = l;
    }
}

__global__ void init_state(float* __restrict__ out) {
    int i = blockIdx.x * blockDim.x + threadIdx.x;
    if (i < BH_) {
        out[i] = 0.0f;
        g_c[i] = 0.0f;
        g_hhi[i] = __float2bfloat16(0.0f);
        g_hlo[i] = __float2bfloat16(0.0f);
    }
    if (i == 0) g_barrier_cnt = 0;   // reset grid barrier each graph replay
}

// ---------------- launch ----------------
#define GEMM_SMEM (2 * 65536)

extern "C" void kernel_launch(void* const* d_in, const int* in_sizes, int n_in,
                              void* d_out, int out_size)
{
    const float* embeds = (const float*)d_in[0];
    const float* Wg = (const float*)d_in[1];
    const float* Wi = (const float*)d_in[2];
    const float* Wf = (const float*)d_in[3];
    const float* Wo = (const float*)d_in[4];
    const float* bg = (const float*)d_in[5];
    const float* bi = (const float*)d_in[6];
    const float* bf = (const float*)d_in[7];
    const float* bo = (const float*)d_in[8];
    float* out = (float*)d_out;

    cudaFuncSetAttribute(gemm_mma, cudaFuncAttributeMaxDynamicSharedMemorySize, GEMM_SMEM);
    cudaFuncSetAttribute(lstm_persistent, cudaFuncAttributeMaxDynamicSharedMemorySize, PK_SMEM);

    __nv_bfloat16 *p_eh, *p_el, *p_wxh, *p_wxl;
    float *p_zx;
    cudaGetSymbolAddress((void**)&p_eh,  g_eh);
    cudaGetSymbolAddress((void**)&p_el,  g_el);
    cudaGetSymbolAddress((void**)&p_wxh, g_wxh);
    cudaGetSymbolAddress((void**)&p_wxl, g_wxl);
    cudaGetSymbolAddress((void**)&p_zx,  g_zx);

    // prep
    {
        int n = T_ * B_ * E_;
        split_plane<<<(n + 255) / 256, 256>>>(embeds, p_eh, p_el, n);
    }
    split_W<<<(4 * 1024 * 2048 + 255) / 256, 256>>>(Wg, Wi, Wf, Wo);
    init_state<<<(BH_ + 255) / 256, 256>>>(out);

    // batch: Zx[t] = x_t @ Wx^T for all t (M = 32768 rows, K = 1024)
    gemm_mma<<<dim3(32, 256, 1), 256, GEMM_SMEM>>>(p_eh, p_el, 1024, p_wxh, p_wxl,
                                                   p_zx, 0, 1024);

    // recurrence: one persistent kernel, all 255 steps
    lstm_persistent<<<PK_CTAS, 256, PK_SMEM>>>(bg, bi, bf, bo, out);
}